// round 2
// baseline (speedup 1.0000x reference)
#include <cuda_runtime.h>
#include <math.h>

#define Bq 4
#define Lq 2048
#define Hq 8
#define Dq 64
#define NSLOT 12   // self + offsets 2^0 .. 2^10

// One warp handles one (b,l): all 8 heads. lane = h*4 + c; lane owns dims
// [c*16, c*16+16) of head h. A (b,l) slab is 512 contiguous floats (2KB).
__global__ __launch_bounds__(256) void logsparse_attn_kernel(
    const float* __restrict__ Q,
    const float* __restrict__ K,
    const float* __restrict__ V,
    float* __restrict__ O)
{
    const int wid  = (blockIdx.x * blockDim.x + threadIdx.x) >> 5;  // = b*L + l
    const int lane = threadIdx.x & 31;
    const int l = wid & (Lq - 1);

    const float4* __restrict__ Q4 = (const float4*)Q;
    const float4* __restrict__ K4 = (const float4*)K;
    const float4* __restrict__ V4 = (const float4*)V;

    // float4 index of this lane's 16-float chunk within the (b,l) slab
    const int slab4 = Hq * Dq / 4;                 // 128 float4 per slab
    const size_t mybase = (size_t)wid * slab4 + lane * 4;

    const float4 q0 = Q4[mybase + 0];
    const float4 q1 = Q4[mybase + 1];
    const float4 q2 = Q4[mybase + 2];
    const float4 q3 = Q4[mybase + 3];

    int   jw[NSLOT];      // slab index of gathered key/value row-group
    float prob[NSLOT];    // scores -> probs in place

    // ---- pass 1: K gather + per-head dot products ----
#pragma unroll
    for (int t = 0; t < NSLOT; t++) {
        const int off = (t == 0) ? 0 : (1 << (t - 1));
        const bool ok = (off <= l);
        const int j = wid - (ok ? off : 0);        // same b (j >= b*L)
        jw[t] = j;
        const size_t kb = (size_t)j * slab4 + lane * 4;
        const float4 k0 = K4[kb + 0];
        const float4 k1 = K4[kb + 1];
        const float4 k2 = K4[kb + 2];
        const float4 k3 = K4[kb + 3];
        float p = q0.x*k0.x + q0.y*k0.y + q0.z*k0.z + q0.w*k0.w
                + q1.x*k1.x + q1.y*k1.y + q1.z*k1.z + q1.w*k1.w
                + q2.x*k2.x + q2.y*k2.y + q2.z*k2.z + q2.w*k2.w
                + q3.x*k3.x + q3.y*k3.y + q3.z*k3.z + q3.w*k3.w;
        // reduce over the 4 lanes of this head (groups aligned at lane%4)
        p += __shfl_xor_sync(0xffffffffu, p, 1);
        p += __shfl_xor_sync(0xffffffffu, p, 2);
        prob[t] = ok ? (p * 0.125f) : -INFINITY;   // 1/sqrt(64)
    }

    // ---- softmax over <=12 entries (computed redundantly per lane) ----
    float mmax = prob[0];
#pragma unroll
    for (int t = 1; t < NSLOT; t++) mmax = fmaxf(mmax, prob[t]);
    float psum = 0.0f;
#pragma unroll
    for (int t = 0; t < NSLOT; t++) {
        const float e = __expf(prob[t] - mmax);    // -inf -> 0
        prob[t] = e;
        psum += e;
    }
    const float inv = 1.0f / psum;
#pragma unroll
    for (int t = 0; t < NSLOT; t++) prob[t] *= inv;

    // ---- pass 2: V gather + weighted accumulate ----
    float4 a0 = {0,0,0,0}, a1 = {0,0,0,0}, a2 = {0,0,0,0}, a3 = {0,0,0,0};
#pragma unroll
    for (int t = 0; t < NSLOT; t++) {
        const size_t vb = (size_t)jw[t] * slab4 + lane * 4;
        const float4 v0 = V4[vb + 0];
        const float4 v1 = V4[vb + 1];
        const float4 v2 = V4[vb + 2];
        const float4 v3 = V4[vb + 3];
        const float p = prob[t];                   // 0 for invalid slots
        a0.x += p*v0.x; a0.y += p*v0.y; a0.z += p*v0.z; a0.w += p*v0.w;
        a1.x += p*v1.x; a1.y += p*v1.y; a1.z += p*v1.z; a1.w += p*v1.w;
        a2.x += p*v2.x; a2.y += p*v2.y; a2.z += p*v2.z; a2.w += p*v2.w;
        a3.x += p*v3.x; a3.y += p*v3.y; a3.z += p*v3.z; a3.w += p*v3.w;
    }

    float4* __restrict__ O4 = (float4*)O;
    O4[mybase + 0] = a0;
    O4[mybase + 1] = a1;
    O4[mybase + 2] = a2;
    O4[mybase + 3] = a3;
}

extern "C" void kernel_launch(void* const* d_in, const int* in_sizes, int n_in,
                              void* d_out, int out_size)
{
    const float* Q = (const float*)d_in[0];
    const float* K = (const float*)d_in[1];
    const float* V = (const float*)d_in[2];
    float* O = (float*)d_out;

    const int total_warps = Bq * Lq;                 // 8192 (one per (b,l))
    const int threads = 256;                         // 8 warps per CTA
    const int blocks = (total_warps * 32) / threads; // 1024
    logsparse_attn_kernel<<<blocks, threads>>>(Q, K, V, O);
}

// round 3
// speedup vs baseline: 2.3654x; 2.3654x over previous
#include <cuda_runtime.h>
#include <math.h>

#define Bq 4
#define Lq 2048
#define Hq 8
#define Dq 64
#define NSLOT 12   // self + offsets 2^0 .. 2^10

// One warp per (b, l, head-pair). The head-pair slab is 128 floats = 32
// contiguous float4; lane ln owns float4 #ln (lanes 0-15 -> even head,
// 16-31 -> odd head). All K/V gathers are whole-slab loads at offsets of
// exactly off*128 float4 (off = 2^(t-1), compile-time), so for l >= 1024
// every address folds to [base + imm].
template <bool FULL>
__device__ __forceinline__ void run_query(
    const float4* __restrict__ Q4, const float4* __restrict__ K4,
    const float4* __restrict__ V4, float4* __restrict__ O4,
    int base4, int l)
{
    const float4 q = Q4[base4];

    float sc[NSLOT];
#pragma unroll
    for (int t = 0; t < NSLOT; t++) {
        const int off = (t == 0) ? 0 : (1 << (t - 1));
        const bool ok = FULL || (off <= l);
        const int kb = base4 - (ok ? off * (Hq * Dq / 4) : 0);
        const float4 k = K4[kb];
        float p = q.x*k.x + q.y*k.y + q.z*k.z + q.w*k.w;
        // reduce over each 16-lane half: both heads at once
        p += __shfl_xor_sync(0xffffffffu, p, 1);
        p += __shfl_xor_sync(0xffffffffu, p, 2);
        p += __shfl_xor_sync(0xffffffffu, p, 4);
        p += __shfl_xor_sync(0xffffffffu, p, 8);
        sc[t] = ok ? (p * 0.125f) : -INFINITY;   // 1/sqrt(64)
    }

    // softmax over <=12 entries (lane-local; lane's half holds its head's scores)
    float m = sc[0];
#pragma unroll
    for (int t = 1; t < NSLOT; t++) m = fmaxf(m, sc[t]);
    float sum = 0.0f;
#pragma unroll
    for (int t = 0; t < NSLOT; t++) {
        const float e = __expf(sc[t] - m);       // -inf -> 0
        sc[t] = e;
        sum += e;
    }
    const float inv = 1.0f / sum;

    float4 acc = {0.f, 0.f, 0.f, 0.f};
#pragma unroll
    for (int t = 0; t < NSLOT; t++) {
        const int off = (t == 0) ? 0 : (1 << (t - 1));
        const bool ok = FULL || (off <= l);
        const int vb = base4 - (ok ? off * (Hq * Dq / 4) : 0);
        const float4 v = V4[vb];
        const float p = sc[t];                   // 0 for invalid slots
        acc.x += p * v.x;
        acc.y += p * v.y;
        acc.z += p * v.z;
        acc.w += p * v.w;
    }
    acc.x *= inv; acc.y *= inv; acc.z *= inv; acc.w *= inv;
    O4[base4] = acc;
}

__global__ __launch_bounds__(256) void logsparse_attn_kernel(
    const float4* __restrict__ Q4,
    const float4* __restrict__ K4,
    const float4* __restrict__ V4,
    float4* __restrict__ O4)
{
    const int wid  = (blockIdx.x * blockDim.x + threadIdx.x) >> 5;
    const int lane = threadIdx.x & 31;
    const int g = wid & (Hq / 2 - 1);        // head-pair index 0..3
    const int s = wid >> 2;                  // b*L + l
    const int l = s & (Lq - 1);

    // float4 index of this lane's 16B chunk
    const int base4 = s * (Hq * Dq / 4) + g * 32 + lane;

    if (l >= 1024) {
        run_query<true>(Q4, K4, V4, O4, base4, l);   // all 12 slots valid
    } else {
        run_query<false>(Q4, K4, V4, O4, base4, l);
    }
}

extern "C" void kernel_launch(void* const* d_in, const int* in_sizes, int n_in,
                              void* d_out, int out_size)
{
    const float4* Q = (const float4*)d_in[0];
    const float4* K = (const float4*)d_in[1];
    const float4* V = (const float4*)d_in[2];
    float4* O = (float4*)d_out;

    const int total_warps = Bq * Lq * (Hq / 2);      // 32768
    const int threads = 256;
    const int blocks = (total_warps * 32) / threads; // 4096
    logsparse_attn_kernel<<<blocks, threads>>>(Q, K, V, O);
}